// round 5
// baseline (speedup 1.0000x reference)
#include <cuda_runtime.h>
#include <cuda_bf16.h>
#include <cstdint>

// ---------------- problem constants ----------------
#define BB   32
#define TT   128
#define LCC  16
#define EE   256
#define ECC  64
#define VCC  128   // char vocab
#define HCC  128   // char bilstm out (64 per dir)
#define HH   512   // word bilstm out
#define KK   12
#define START_T 10
#define STOP_T  11
#define NEGV -10000.0f

#define BT   (BB*TT)            // 4096
#define INW  (EE + HCC)         // 384
#define HW   256                // word hidden per dir
#define GW   1024               // 4*HW
#define HCD  64                 // char hidden per dir
#define GC   256                // 4*HCD
#define NBW  128                // persistent blocks (grid barrier)

// ---------------- scratch ----------------
__device__ float g_ctab_f[VCC * GC];             // per-char fwd gate table
__device__ float g_ctab_b[VCC * GC];             // per-char bwd gate table
__device__ float g_chout[(size_t)BT * HCC];
__device__ float g_wx[(size_t)BT * INW];
__device__ float g_wpf[(size_t)BT * GW];         // layout [t][b][n]
__device__ float g_wpb[(size_t)BT * GW];         // layout [t][b][n]
__device__ float g_h[2 * 2 * HW * BB];           // [parity][dir][j][b]
__device__ float g_wh[(size_t)2 * BT * HW];      // [dir][b*T+t][j]
__device__ float g_feats[(size_t)BT * KK];

// distributed barrier flags (reset each launch -> deterministic across replays)
__device__ volatile unsigned g_flags[NBW];

__device__ __forceinline__ float sigf(float x) { return 1.0f / (1.0f + expf(-x)); }

// ---------------- packed f32x2 helpers (sm_100+) ----------------
__device__ __forceinline__ unsigned long long fma2(unsigned long long a,
                                                   unsigned long long b,
                                                   unsigned long long c)
{
    unsigned long long d;
    asm("fma.rn.f32x2 %0, %1, %2, %3;" : "=l"(d) : "l"(a), "l"(b), "l"(c));
    return d;
}
__device__ __forceinline__ unsigned long long pack2(float x, float y)
{
    unsigned long long d;
    asm("mov.b64 %0, {%1, %2};" : "=l"(d) : "f"(x), "f"(y));
    return d;
}
__device__ __forceinline__ void unpack2(unsigned long long v, float& x, float& y)
{
    asm("mov.b64 {%0, %1}, %2;" : "=f"(x), "=f"(y) : "l"(v));
}

// ---------------- char projection tables: tab[cid][g] = emb[cid] @ Wih^T + b ----------------
__global__ void char_table_kernel(const float* __restrict__ char_emb,
                                  const float* __restrict__ Wih_f, const float* __restrict__ b_f,
                                  const float* __restrict__ Wih_b, const float* __restrict__ b_b)
{
    const int cid = blockIdx.x;
    const int dir = blockIdx.y;
    const int j = threadIdx.x;           // 0..255 gate index
    __shared__ float e[ECC];
    if (j < ECC) e[j] = char_emb[cid * ECC + j];
    __syncthreads();
    const float* Wih = dir ? Wih_b : Wih_f;
    const float* bias = dir ? b_b : b_f;
    const float* row = Wih + (size_t)j * ECC;
    float acc = bias[j];
#pragma unroll 8
    for (int k = 0; k < ECC; k++) acc += row[k] * e[k];
    (dir ? g_ctab_b : g_ctab_f)[cid * GC + j] = acc;
}

// ---------------- char BiLSTM (fwd recurrence + bwd single step), one block per word ----------------
__global__ void char_fwd_kernel(const int* __restrict__ chars,
                                const float* __restrict__ Whh, float* __restrict__ chout)
{
    const int bt = blockIdx.x;
    const int j = threadIdx.x;   // 256 threads = gate index
    __shared__ __align__(16) float hs[HCD];
    __shared__ float gs[GC];
    __shared__ int cid[LCC];

    if (j < LCC) cid[j] = chars[bt * LCC + j];

    float4 w4[16];
    const float4* wr = (const float4*)(Whh + (size_t)j * HCD);
#pragma unroll
    for (int i = 0; i < 16; i++) w4[i] = wr[i];

    float c = 0.0f;
    if (j < HCD) hs[j] = 0.0f;
    __syncthreads();

    for (int t = 0; t < LCC; t++) {
        float acc = g_ctab_f[cid[t] * GC + j];
#pragma unroll
        for (int kk = 0; kk < 16; kk++) {
            float4 h4 = *(const float4*)&hs[kk << 2];
            acc += w4[kk].x * h4.x + w4[kk].y * h4.y + w4[kk].z * h4.z + w4[kk].w * h4.w;
        }
        gs[j] = acc;
        __syncthreads();
        if (j < HCD) {
            float gi = gs[j], gf = gs[HCD + j], gg = gs[2 * HCD + j], go = gs[3 * HCD + j];
            c = sigf(gf) * c + sigf(gi) * tanhf(gg);
            hs[j] = sigf(go) * tanhf(c);
        }
        __syncthreads();
    }
    if (j < HCD) {
        chout[(size_t)bt * HCC + j] = hs[j];
        // backward dir: take-last == one step on last char from zero state
        const float* row = g_ctab_b + cid[LCC - 1] * GC;
        float gi = row[j], gg = row[2 * HCD + j], go = row[3 * HCD + j];
        float cb = sigf(gi) * tanhf(gg);
        chout[(size_t)bt * HCC + HCD + j] = sigf(go) * tanhf(cb);
    }
}

// ---------------- build word-lstm input x = [ch, we] ----------------
__global__ void build_wx_kernel(const int* __restrict__ sentence,
                                const float* __restrict__ word_emb)
{
    int idx = blockIdx.x * blockDim.x + threadIdx.x;
    if (idx >= BT * INW) return;
    int bt = idx / INW, cpos = idx % INW;
    float v;
    if (cpos < HCC) v = g_chout[(size_t)bt * HCC + cpos];
    else            v = word_emb[(size_t)sentence[bt] * EE + (cpos - HCC)];
    g_wx[idx] = v;
}

// ---------------- word projection GEMM: C = wx @ W^T + b, output layout [t][b][n] ----------------
// 128x128 tile, 256 threads, 8x8 microtile, packed f32x2 accumulators,
// double-buffered smem with register prefetch.
#define NKT (INW / 16)   // 24 k-tiles
__global__ void __launch_bounds__(256, 2)
wproj_gemm(const float* __restrict__ Wf, const float* __restrict__ bf_,
           const float* __restrict__ Wb, const float* __restrict__ bb_)
{
    const float* W    = blockIdx.z ? Wb : Wf;
    const float* bias = blockIdx.z ? bb_ : bf_;
    float* C          = blockIdx.z ? g_wpb : g_wpf;

    __shared__ __align__(16) float As[2][16][128];
    __shared__ __align__(16) float Bs[2][16][128];

    const int m0 = blockIdx.y * 128;      // m = b*T + t; 128-aligned -> b fixed per block
    const int n0 = blockIdx.x * 128;
    const int bglob = blockIdx.y;         // batch index for this block
    const int tid = threadIdx.x;
    const int tx = tid & 15, ty = tid >> 4;

    // per-thread load coords (2 chunks of 256 ids)
    const int row0 = tid >> 2,          q0 = tid & 3;
    const int row1 = (tid + 256) >> 2,  q1 = (tid + 256) & 3;

    float4 pa0, pa1, pw0, pw1;
#define WP_LOAD(k0)                                                            \
    do {                                                                       \
        pa0 = *(const float4*)&g_wx[(size_t)(m0 + row0) * INW + (k0) + q0 * 4];\
        pw0 = *(const float4*)&W[(size_t)(n0 + row0) * INW + (k0) + q0 * 4];   \
        pa1 = *(const float4*)&g_wx[(size_t)(m0 + row1) * INW + (k0) + q1 * 4];\
        pw1 = *(const float4*)&W[(size_t)(n0 + row1) * INW + (k0) + q1 * 4];   \
    } while (0)
#define WP_STORE(buf)                                                          \
    do {                                                                       \
        As[buf][q0 * 4 + 0][row0] = pa0.x; As[buf][q0 * 4 + 1][row0] = pa0.y;  \
        As[buf][q0 * 4 + 2][row0] = pa0.z; As[buf][q0 * 4 + 3][row0] = pa0.w;  \
        Bs[buf][q0 * 4 + 0][row0] = pw0.x; Bs[buf][q0 * 4 + 1][row0] = pw0.y;  \
        Bs[buf][q0 * 4 + 2][row0] = pw0.z; Bs[buf][q0 * 4 + 3][row0] = pw0.w;  \
        As[buf][q1 * 4 + 0][row1] = pa1.x; As[buf][q1 * 4 + 1][row1] = pa1.y;  \
        As[buf][q1 * 4 + 2][row1] = pa1.z; As[buf][q1 * 4 + 3][row1] = pa1.w;  \
        Bs[buf][q1 * 4 + 0][row1] = pw1.x; Bs[buf][q1 * 4 + 1][row1] = pw1.y;  \
        Bs[buf][q1 * 4 + 2][row1] = pw1.z; Bs[buf][q1 * 4 + 3][row1] = pw1.w;  \
    } while (0)

    unsigned long long acc2[8][4];
#pragma unroll
    for (int i = 0; i < 8; i++)
#pragma unroll
        for (int jp = 0; jp < 4; jp++) acc2[i][jp] = 0ull;

    WP_LOAD(0);
    WP_STORE(0);
    __syncthreads();

    for (int kt = 0; kt < NKT; kt++) {
        const int cur = kt & 1;
        if (kt + 1 < NKT) WP_LOAD((kt + 1) * 16);
#pragma unroll
        for (int k = 0; k < 16; k++) {
            float4 a0 = *(const float4*)&As[cur][k][ty * 8];
            float4 a1 = *(const float4*)&As[cur][k][ty * 8 + 4];
            ulonglong2 b0 = *(const ulonglong2*)&Bs[cur][k][tx * 8];
            ulonglong2 b1 = *(const ulonglong2*)&Bs[cur][k][tx * 8 + 4];
            float aarr[8] = {a0.x, a0.y, a0.z, a0.w, a1.x, a1.y, a1.z, a1.w};
#pragma unroll
            for (int i = 0; i < 8; i++) {
                unsigned long long ad = pack2(aarr[i], aarr[i]);
                acc2[i][0] = fma2(ad, b0.x, acc2[i][0]);
                acc2[i][1] = fma2(ad, b0.y, acc2[i][1]);
                acc2[i][2] = fma2(ad, b1.x, acc2[i][2]);
                acc2[i][3] = fma2(ad, b1.y, acc2[i][3]);
            }
        }
        if (kt + 1 < NKT) {
            WP_STORE(cur ^ 1);
            __syncthreads();
        }
    }

#pragma unroll
    for (int i = 0; i < 8; i++) {
        int t = ty * 8 + i;               // local m == t (b fixed)
        size_t base = ((size_t)t * BB + bglob) * GW;
#pragma unroll
        for (int jp = 0; jp < 4; jp++) {
            int n = n0 + tx * 8 + jp * 2;
            float c0, c1;
            unpack2(acc2[i][jp], c0, c1);
            float2 v = make_float2(c0 + __ldg(&bias[n]), c1 + __ldg(&bias[n + 1]));
            *(float2*)&C[base + n] = v;
        }
    }
}

// ---------------- barrier reset (determinism across graph replays) ----------------
__global__ void reset_bar()
{
    if (threadIdx.x < NBW) g_flags[threadIdx.x] = 0;
}

// ---------------- persistent word BiLSTM, distributed-flag grid barrier ----------------
__global__ void word_lstm_kernel(const float* __restrict__ Whhf,
                                 const float* __restrict__ Whhb)
{
    extern __shared__ float sm[];
    float* ws = sm;                 // 4096 floats: [jh_l][k][gate(4)]
    float* hs = sm + 4096;          // 8192 floats: [k][b]

    const int tid = threadIdx.x;          // 0..127
    const int dir = blockIdx.x >> 6;
    const int chunk = blockIdx.x & 63;
    const int jh0 = chunk * 4;
    const int jh_l = tid >> 5;            // 0..3
    const int b = tid & 31;
    const int jh = jh0 + jh_l;

    const float* Whh = dir ? Whhb : Whhf;
    const float* xp  = dir ? g_wpb : g_wpf;

    // stage weight slice once: ws[jl*1024 + k*4 + gate]
    for (int i = tid; i < 4096; i += 128) {
        int gate = i & 3;
        int k = (i >> 2) & 255;
        int jl = i >> 10;
        ws[i] = Whh[(size_t)((gate << 8) + jh0 + jl) * HW + k];
    }
    __syncthreads();

    const ulonglong2* wv = (const ulonglong2*)ws + (jh_l << 8);

    float xi, xf2, xg, xo;
    {
        int t0 = dir ? (TT - 1) : 0;
        const float* base = xp + ((size_t)t0 * BB + b) * GW;
        xi = base[jh]; xf2 = base[HW + jh]; xg = base[2 * HW + jh]; xo = base[3 * HW + jh];
    }

    float c = 0.0f;
    for (int s = 0; s < TT; s++) {
        const int t = dir ? (TT - 1 - s) : s;
        unsigned long long acc_if = pack2(xi, xf2);
        unsigned long long acc_go = pack2(xg, xo);
        if (s > 0) {
            const float4* hsrc = (const float4*)(g_h + (((s & 1) * 2 + dir) << 13));
            float4* hd4 = (float4*)hs;
#pragma unroll
            for (int i = tid; i < 2048; i += 128) hd4[i] = __ldcg(hsrc + i);
            __syncthreads();
#pragma unroll 8
            for (int k = 0; k < 256; k++) {
                ulonglong2 w = wv[k];
                float hv = hs[(k << 5) + b];
                unsigned long long hd = pack2(hv, hv);
                acc_if = fma2(hd, w.x, acc_if);
                acc_go = fma2(hd, w.y, acc_go);
            }
        }
        float gi, gf, gg, go;
        unpack2(acc_if, gi, gf);
        unpack2(acc_go, gg, go);
        c = sigf(gf) * c + sigf(gi) * tanhf(gg);
        float h = sigf(go) * tanhf(c);

        __stcg(g_h + (((((s + 1) & 1) * 2 + dir) << 13) + (jh << 5) + b), h);
        g_wh[((size_t)dir * BT + b * TT + t) * HW + jh] = h;

        if (s + 1 < TT) {
            // prefetch next x while the barrier settles
            int tn = dir ? (TT - 2 - s) : (s + 1);
            const float* base = xp + ((size_t)tn * BB + b) * GW;
            xi = base[jh]; xf2 = base[HW + jh]; xg = base[2 * HW + jh]; xo = base[3 * HW + jh];

            // distributed-flag grid barrier: parallel arrive, parallel wait
            const unsigned want = (unsigned)(s + 1);
            __threadfence();
            __syncthreads();
            if (tid == 0) g_flags[blockIdx.x] = want;
            while (g_flags[tid] < want) { }
            __threadfence();
            __syncthreads();
        }
    }
}

// ---------------- feats: warp per (bt,k) dot over 512 ----------------
__global__ void feats_kernel(const float* __restrict__ W2t, const float* __restrict__ b2t)
{
    const unsigned full = 0xffffffffu;
    int gwarp = (blockIdx.x * blockDim.x + threadIdx.x) >> 5;
    if (gwarp >= BT * KK) return;
    int lane = threadIdx.x & 31;
    int bt = gwarp / KK, k = gwarp % KK;

    const float4* hf = (const float4*)(g_wh + (size_t)bt * HW);
    const float4* hb = (const float4*)(g_wh + ((size_t)BT + bt) * HW);
    const float4* w  = (const float4*)(W2t + (size_t)k * HH);

    float acc = 0.0f;
#pragma unroll
    for (int u = 0; u < 2; u++) {
        float4 h4 = hf[lane * 2 + u];
        float4 w4 = w[lane * 2 + u];
        acc += h4.x * w4.x + h4.y * w4.y + h4.z * w4.z + h4.w * w4.w;
    }
#pragma unroll
    for (int u = 0; u < 2; u++) {
        float4 h4 = hb[lane * 2 + u];
        float4 w4 = w[64 + lane * 2 + u];
        acc += h4.x * w4.x + h4.y * w4.y + h4.z * w4.z + h4.w * w4.w;
    }
#pragma unroll
    for (int off = 16; off > 0; off >>= 1) acc += __shfl_xor_sync(full, acc, off);
    if (lane == 0) g_feats[bt * KK + k] = acc + b2t[k];
}

// ---------------- CRF forward + gold + final reduction ----------------
__global__ void crf_kernel(const int* __restrict__ tags, const float* __restrict__ trans,
                           float* __restrict__ out)
{
    __shared__ float res[BB];
    const int lane = threadIdx.x & 31;
    const int b = threadIdx.x >> 5;
    const unsigned full = 0xffffffffu;

    int kr = (lane < KK) ? lane : 0;
    float trow[KK];
#pragma unroll
    for (int j = 0; j < KK; j++) trow[j] = trans[kr * KK + j];

    float alpha = (lane == START_T) ? 0.0f : NEGV;

    for (int t = 0; t < TT; t++) {
        float vals[KK];
        float m = -INFINITY;
#pragma unroll
        for (int j = 0; j < KK; j++) {
            float aj = __shfl_sync(full, alpha, j);
            float v = aj + trow[j];
            vals[j] = v;
            m = fmaxf(m, v);
        }
        float s = 0.0f;
#pragma unroll
        for (int j = 0; j < KK; j++) s += expf(vals[j] - m);
        alpha = m + logf(s) + g_feats[(size_t)(b * TT + t) * KK + kr];
    }

    float v = (lane < KK) ? (alpha + trans[STOP_T * KK + lane]) : -INFINITY;
    float m = v;
#pragma unroll
    for (int off = 16; off > 0; off >>= 1) m = fmaxf(m, __shfl_xor_sync(full, m, off));
    float e = (lane < KK) ? expf(v - m) : 0.0f;
#pragma unroll
    for (int off = 16; off > 0; off >>= 1) e += __shfl_xor_sync(full, e, off);
    float fwd = m + logf(e);

    float gold = 0.0f;
    for (int t = lane; t < TT; t += 32) {
        int tg = tags[b * TT + t];
        gold += g_feats[(size_t)(b * TT + t) * KK + tg];
        int prev = (t == 0) ? START_T : tags[b * TT + t - 1];
        gold += trans[tg * KK + prev];
    }
#pragma unroll
    for (int off = 16; off > 0; off >>= 1) gold += __shfl_xor_sync(full, gold, off);

    if (lane == 0) {
        gold += trans[STOP_T * KK + tags[b * TT + TT - 1]];
        res[b] = fwd - gold;
    }
    __syncthreads();
    if (threadIdx.x == 0) {
        float s = 0.0f;
        for (int i = 0; i < BB; i++) s += res[i];
        out[0] = s / (float)BB;
    }
}

// ---------------- launch ----------------
extern "C" void kernel_launch(void* const* d_in, const int* in_sizes, int n_in,
                              void* d_out, int out_size)
{
    const int*   sentence = (const int*)d_in[0];
    const int*   chars    = (const int*)d_in[1];
    const int*   tags     = (const int*)d_in[2];
    const float* word_emb = (const float*)d_in[3];
    const float* char_emb = (const float*)d_in[4];
    const float* c_Wih_f  = (const float*)d_in[5];
    const float* c_Whh_f  = (const float*)d_in[6];
    const float* c_b_f    = (const float*)d_in[7];
    const float* c_Wih_b  = (const float*)d_in[8];
    const float* c_Whh_b  = (const float*)d_in[9];   (void)c_Whh_b;
    const float* c_b_b    = (const float*)d_in[10];
    const float* w_Wih_f  = (const float*)d_in[11];
    const float* w_Whh_f  = (const float*)d_in[12];
    const float* w_b_f    = (const float*)d_in[13];
    const float* w_Wih_b  = (const float*)d_in[14];
    const float* w_Whh_b  = (const float*)d_in[15];
    const float* w_b_b    = (const float*)d_in[16];
    const float* W2t      = (const float*)d_in[17];
    const float* b2t      = (const float*)d_in[18];
    const float* trans    = (const float*)d_in[19];
    float* out = (float*)d_out;

    float* chout; cudaGetSymbolAddress((void**)&chout, g_chout);

    // 1) char gate tables (both dirs)
    char_table_kernel<<<dim3(VCC, 2), GC>>>(char_emb, c_Wih_f, c_b_f, c_Wih_b, c_b_b);
    // 2) char BiLSTM (fwd recurrence + bwd single step), table-driven
    char_fwd_kernel<<<BT, GC>>>(chars, c_Whh_f, chout);
    // 3) build word input
    build_wx_kernel<<<(BT * INW + 255) / 256, 256>>>(sentence, word_emb);
    // 4) word input projections (both dirs in one launch)
    wproj_gemm<<<dim3(GW / 128, BT / 128, 2), 256>>>(w_Wih_f, w_b_f, w_Wih_b, w_b_b);
    // 5) barrier reset + persistent word BiLSTM
    reset_bar<<<1, NBW>>>();
    word_lstm_kernel<<<NBW, 128, 48 * 1024>>>(w_Whh_f, w_Whh_b);
    // 6) feats
    feats_kernel<<<(BT * KK * 32 + 255) / 256, 256>>>(W2t, b2t);
    // 7) CRF + output
    crf_kernel<<<1, BB * 32>>>(tags, trans, out);

    (void)in_sizes; (void)n_in; (void)out_size;
}

// round 6
// speedup vs baseline: 1.5032x; 1.5032x over previous
#include <cuda_runtime.h>
#include <cuda_bf16.h>
#include <cstdint>

// ---------------- problem constants ----------------
#define BB   32
#define TT   128
#define LCC  16
#define EE   256
#define ECC  64
#define VCC  128   // char vocab
#define HCC  128   // char bilstm out (64 per dir)
#define HH   512   // word bilstm out
#define KK   12
#define START_T 10
#define STOP_T  11
#define NEGV -10000.0f

#define BT   (BB*TT)            // 4096
#define INW  (EE + HCC)         // 384
#define HW   256                // word hidden per dir
#define GW   1024               // 4*HW
#define HCD  64                 // char hidden per dir
#define GC   256                // 4*HCD
#define NBW  128                // persistent blocks (grid barrier)

// ---------------- scratch ----------------
__device__ float g_ctab_f[VCC * GC];             // per-char fwd gate table
__device__ float g_ctab_b[VCC * GC];             // per-char bwd gate table
__device__ float g_chout[(size_t)BT * HCC];
__device__ float g_wx[(size_t)BT * INW];
__device__ float g_wpf[(size_t)BT * GW];         // layout [t][b][n]
__device__ float g_wpb[(size_t)BT * GW];         // layout [t][b][n]
__device__ float g_h[2 * 2 * HW * BB];           // [parity][dir][j][b]
__device__ float g_wh[(size_t)2 * BT * HW];      // [dir][b*T+t][j]
__device__ float g_feats[(size_t)BT * KK];

// distributed barrier flags, padded to one 32B sector per block
__device__ unsigned g_flags[NBW * 8];

__device__ __forceinline__ float sigf(float x) { return 1.0f / (1.0f + expf(-x)); }

// ---------------- packed f32x2 helpers (sm_100+) ----------------
__device__ __forceinline__ unsigned long long fma2(unsigned long long a,
                                                   unsigned long long b,
                                                   unsigned long long c)
{
    unsigned long long d;
    asm("fma.rn.f32x2 %0, %1, %2, %3;" : "=l"(d) : "l"(a), "l"(b), "l"(c));
    return d;
}
__device__ __forceinline__ unsigned long long pack2(float x, float y)
{
    unsigned long long d;
    asm("mov.b64 %0, {%1, %2};" : "=l"(d) : "f"(x), "f"(y));
    return d;
}
__device__ __forceinline__ void unpack2(unsigned long long v, float& x, float& y)
{
    asm("mov.b64 {%0, %1}, %2;" : "=f"(x), "=f"(y) : "l"(v));
}

// ---------------- char projection tables: tab[cid][g] = emb[cid] @ Wih^T + b ----------------
__global__ void char_table_kernel(const float* __restrict__ char_emb,
                                  const float* __restrict__ Wih_f, const float* __restrict__ b_f,
                                  const float* __restrict__ Wih_b, const float* __restrict__ b_b)
{
    const int cid = blockIdx.x;
    const int dir = blockIdx.y;
    const int j = threadIdx.x;           // 0..255 gate index
    __shared__ float e[ECC];
    if (j < ECC) e[j] = char_emb[cid * ECC + j];
    __syncthreads();
    const float* Wih = dir ? Wih_b : Wih_f;
    const float* bias = dir ? b_b : b_f;
    const float* row = Wih + (size_t)j * ECC;
    float acc = bias[j];
#pragma unroll 8
    for (int k = 0; k < ECC; k++) acc += row[k] * e[k];
    (dir ? g_ctab_b : g_ctab_f)[cid * GC + j] = acc;
}

// ---------------- char BiLSTM (fwd recurrence + bwd single step), one block per word ----------------
__global__ void char_fwd_kernel(const int* __restrict__ chars,
                                const float* __restrict__ Whh, float* __restrict__ chout)
{
    const int bt = blockIdx.x;
    const int j = threadIdx.x;   // 256 threads = gate index
    __shared__ __align__(16) float hs[HCD];
    __shared__ float gs[GC];
    __shared__ int cid[LCC];

    if (j < LCC) cid[j] = chars[bt * LCC + j];

    float4 w4[16];
    const float4* wr = (const float4*)(Whh + (size_t)j * HCD);
#pragma unroll
    for (int i = 0; i < 16; i++) w4[i] = wr[i];

    float c = 0.0f;
    if (j < HCD) hs[j] = 0.0f;
    __syncthreads();

    for (int t = 0; t < LCC; t++) {
        float acc = g_ctab_f[cid[t] * GC + j];
#pragma unroll
        for (int kk = 0; kk < 16; kk++) {
            float4 h4 = *(const float4*)&hs[kk << 2];
            acc += w4[kk].x * h4.x + w4[kk].y * h4.y + w4[kk].z * h4.z + w4[kk].w * h4.w;
        }
        gs[j] = acc;
        __syncthreads();
        if (j < HCD) {
            float gi = gs[j], gf = gs[HCD + j], gg = gs[2 * HCD + j], go = gs[3 * HCD + j];
            c = sigf(gf) * c + sigf(gi) * tanhf(gg);
            hs[j] = sigf(go) * tanhf(c);
        }
        __syncthreads();
    }
    if (j < HCD) {
        chout[(size_t)bt * HCC + j] = hs[j];
        // backward dir: take-last == one step on last char from zero state
        const float* row = g_ctab_b + cid[LCC - 1] * GC;
        float gi = row[j], gg = row[2 * HCD + j], go = row[3 * HCD + j];
        float cb = sigf(gi) * tanhf(gg);
        chout[(size_t)bt * HCC + HCD + j] = sigf(go) * tanhf(cb);
    }
}

// ---------------- build word-lstm input x = [ch, we] ----------------
__global__ void build_wx_kernel(const int* __restrict__ sentence,
                                const float* __restrict__ word_emb)
{
    int idx = blockIdx.x * blockDim.x + threadIdx.x;
    if (idx >= BT * INW) return;
    int bt = idx / INW, cpos = idx % INW;
    float v;
    if (cpos < HCC) v = g_chout[(size_t)bt * HCC + cpos];
    else            v = word_emb[(size_t)sentence[bt] * EE + (cpos - HCC)];
    g_wx[idx] = v;
}

// ---------------- word projection GEMM: C = wx @ W^T + b, output layout [t][b][n] ----------------
// 128x128 tile, 256 threads, 8x8 microtile, packed f32x2 accumulators,
// double-buffered smem with register prefetch.
#define NKT (INW / 16)   // 24 k-tiles
__global__ void __launch_bounds__(256, 2)
wproj_gemm(const float* __restrict__ Wf, const float* __restrict__ bf_,
           const float* __restrict__ Wb, const float* __restrict__ bb_)
{
    const float* W    = blockIdx.z ? Wb : Wf;
    const float* bias = blockIdx.z ? bb_ : bf_;
    float* C          = blockIdx.z ? g_wpb : g_wpf;

    __shared__ __align__(16) float As[2][16][128];
    __shared__ __align__(16) float Bs[2][16][128];

    const int m0 = blockIdx.y * 128;      // m = b*T + t; 128-aligned -> b fixed per block
    const int n0 = blockIdx.x * 128;
    const int bglob = blockIdx.y;         // batch index for this block
    const int tid = threadIdx.x;
    const int tx = tid & 15, ty = tid >> 4;

    // per-thread load coords (2 chunks of 256 ids)
    const int row0 = tid >> 2,          q0 = tid & 3;
    const int row1 = (tid + 256) >> 2,  q1 = (tid + 256) & 3;

    float4 pa0, pa1, pw0, pw1;
#define WP_LOAD(k0)                                                            \
    do {                                                                       \
        pa0 = *(const float4*)&g_wx[(size_t)(m0 + row0) * INW + (k0) + q0 * 4];\
        pw0 = *(const float4*)&W[(size_t)(n0 + row0) * INW + (k0) + q0 * 4];   \
        pa1 = *(const float4*)&g_wx[(size_t)(m0 + row1) * INW + (k0) + q1 * 4];\
        pw1 = *(const float4*)&W[(size_t)(n0 + row1) * INW + (k0) + q1 * 4];   \
    } while (0)
#define WP_STORE(buf)                                                          \
    do {                                                                       \
        As[buf][q0 * 4 + 0][row0] = pa0.x; As[buf][q0 * 4 + 1][row0] = pa0.y;  \
        As[buf][q0 * 4 + 2][row0] = pa0.z; As[buf][q0 * 4 + 3][row0] = pa0.w;  \
        Bs[buf][q0 * 4 + 0][row0] = pw0.x; Bs[buf][q0 * 4 + 1][row0] = pw0.y;  \
        Bs[buf][q0 * 4 + 2][row0] = pw0.z; Bs[buf][q0 * 4 + 3][row0] = pw0.w;  \
        As[buf][q1 * 4 + 0][row1] = pa1.x; As[buf][q1 * 4 + 1][row1] = pa1.y;  \
        As[buf][q1 * 4 + 2][row1] = pa1.z; As[buf][q1 * 4 + 3][row1] = pa1.w;  \
        Bs[buf][q1 * 4 + 0][row1] = pw1.x; Bs[buf][q1 * 4 + 1][row1] = pw1.y;  \
        Bs[buf][q1 * 4 + 2][row1] = pw1.z; Bs[buf][q1 * 4 + 3][row1] = pw1.w;  \
    } while (0)

    unsigned long long acc2[8][4];
#pragma unroll
    for (int i = 0; i < 8; i++)
#pragma unroll
        for (int jp = 0; jp < 4; jp++) acc2[i][jp] = 0ull;

    WP_LOAD(0);
    WP_STORE(0);
    __syncthreads();

    for (int kt = 0; kt < NKT; kt++) {
        const int cur = kt & 1;
        if (kt + 1 < NKT) WP_LOAD((kt + 1) * 16);
#pragma unroll
        for (int k = 0; k < 16; k++) {
            float4 a0 = *(const float4*)&As[cur][k][ty * 8];
            float4 a1 = *(const float4*)&As[cur][k][ty * 8 + 4];
            ulonglong2 b0 = *(const ulonglong2*)&Bs[cur][k][tx * 8];
            ulonglong2 b1 = *(const ulonglong2*)&Bs[cur][k][tx * 8 + 4];
            float aarr[8] = {a0.x, a0.y, a0.z, a0.w, a1.x, a1.y, a1.z, a1.w};
#pragma unroll
            for (int i = 0; i < 8; i++) {
                unsigned long long ad = pack2(aarr[i], aarr[i]);
                acc2[i][0] = fma2(ad, b0.x, acc2[i][0]);
                acc2[i][1] = fma2(ad, b0.y, acc2[i][1]);
                acc2[i][2] = fma2(ad, b1.x, acc2[i][2]);
                acc2[i][3] = fma2(ad, b1.y, acc2[i][3]);
            }
        }
        if (kt + 1 < NKT) {
            WP_STORE(cur ^ 1);
            __syncthreads();
        }
    }

#pragma unroll
    for (int i = 0; i < 8; i++) {
        int t = ty * 8 + i;               // local m == t (b fixed)
        size_t base = ((size_t)t * BB + bglob) * GW;
#pragma unroll
        for (int jp = 0; jp < 4; jp++) {
            int n = n0 + tx * 8 + jp * 2;
            float c0, c1;
            unpack2(acc2[i][jp], c0, c1);
            float2 v = make_float2(c0 + __ldg(&bias[n]), c1 + __ldg(&bias[n + 1]));
            *(float2*)&C[base + n] = v;
        }
    }
}

// ---------------- barrier reset (determinism across graph replays) ----------------
__global__ void reset_bar()
{
    for (int i = threadIdx.x; i < NBW * 8; i += blockDim.x) g_flags[i] = 0;
}

// ---------------- persistent word BiLSTM, padded-flag grid barrier ----------------
// Arrival: one cg store per block (parallel). Wait: 2 warps per block, one
// dir-local flag per lane, dependent-load spin (one poll per L2 round-trip).
__global__ void word_lstm_kernel(const float* __restrict__ Whhf,
                                 const float* __restrict__ Whhb)
{
    extern __shared__ float sm[];
    float* ws = sm;                 // 4096 floats: [jh_l][k][gate(4)]
    float* hs = sm + 4096;          // 8192 floats: [k][b]

    const int tid = threadIdx.x;          // 0..127
    const int dir = blockIdx.x >> 6;
    const int chunk = blockIdx.x & 63;
    const int jh0 = chunk * 4;
    const int jh_l = tid >> 5;            // 0..3
    const int b = tid & 31;
    const int jh = jh0 + jh_l;

    const float* Whh = dir ? Whhb : Whhf;
    const float* xp  = dir ? g_wpb : g_wpf;

    // stage weight slice once: ws[jl*1024 + k*4 + gate]
    for (int i = tid; i < 4096; i += 128) {
        int gate = i & 3;
        int k = (i >> 2) & 255;
        int jl = i >> 10;
        ws[i] = Whh[(size_t)((gate << 8) + jh0 + jl) * HW + k];
    }
    __syncthreads();

    const ulonglong2* wv = (const ulonglong2*)ws + (jh_l << 8);

    unsigned* myflag   = g_flags + blockIdx.x * 8;
    // this thread's poll target (warps 0/1 only): dir-local block (dir<<6 | w*32+lane)
    unsigned* pollflag = g_flags + (((dir << 6) + tid) * 8);

    float xi, xf2, xg, xo;
    {
        int t0 = dir ? (TT - 1) : 0;
        const float* base = xp + ((size_t)t0 * BB + b) * GW;
        xi = base[jh]; xf2 = base[HW + jh]; xg = base[2 * HW + jh]; xo = base[3 * HW + jh];
    }

    float c = 0.0f;
    for (int s = 0; s < TT; s++) {
        const int t = dir ? (TT - 1 - s) : s;
        unsigned long long acc_if = pack2(xi, xf2);
        unsigned long long acc_go = pack2(xg, xo);
        if (s > 0) {
            const float4* hsrc = (const float4*)(g_h + (((s & 1) * 2 + dir) << 13));
            float4* hd4 = (float4*)hs;
#pragma unroll
            for (int i = tid; i < 2048; i += 128) hd4[i] = __ldcg(hsrc + i);
            __syncthreads();
#pragma unroll 8
            for (int k = 0; k < 256; k++) {
                ulonglong2 w = wv[k];
                float hv = hs[(k << 5) + b];
                unsigned long long hd = pack2(hv, hv);
                acc_if = fma2(hd, w.x, acc_if);
                acc_go = fma2(hd, w.y, acc_go);
            }
        }
        float gi, gf, gg, go;
        unpack2(acc_if, gi, gf);
        unpack2(acc_go, gg, go);
        c = sigf(gf) * c + sigf(gi) * tanhf(gg);
        float h = sigf(go) * tanhf(c);

        __stcg(g_h + (((((s + 1) & 1) * 2 + dir) << 13) + (jh << 5) + b), h);
        g_wh[((size_t)dir * BT + b * TT + t) * HW + jh] = h;

        if (s + 1 < TT) {
            // prefetch next x while the barrier settles
            int tn = dir ? (TT - 2 - s) : (s + 1);
            const float* base = xp + ((size_t)tn * BB + b) * GW;
            xi = base[jh]; xf2 = base[HW + jh]; xg = base[2 * HW + jh]; xo = base[3 * HW + jh];

            const unsigned want = (unsigned)(s + 1);
            __threadfence();
            __syncthreads();
            if (tid == 0) {
                asm volatile("st.global.cg.u32 [%0], %1;" :: "l"(myflag), "r"(want) : "memory");
            }
            if (tid < 64) {   // warps 0,1: poll 64 dir-local flags, one per lane
                unsigned v;
                do {
                    asm volatile("ld.global.cg.u32 %0, [%1];" : "=r"(v) : "l"(pollflag) : "memory");
                } while (v < want);
            }
            __syncthreads();
            __threadfence();
        }
    }
}

// ---------------- feats: warp per (bt,k) dot over 512 ----------------
__global__ void feats_kernel(const float* __restrict__ W2t, const float* __restrict__ b2t)
{
    const unsigned full = 0xffffffffu;
    int gwarp = (blockIdx.x * blockDim.x + threadIdx.x) >> 5;
    if (gwarp >= BT * KK) return;
    int lane = threadIdx.x & 31;
    int bt = gwarp / KK, k = gwarp % KK;

    const float4* hf = (const float4*)(g_wh + (size_t)bt * HW);
    const float4* hb = (const float4*)(g_wh + ((size_t)BT + bt) * HW);
    const float4* w  = (const float4*)(W2t + (size_t)k * HH);

    float acc = 0.0f;
#pragma unroll
    for (int u = 0; u < 2; u++) {
        float4 h4 = hf[lane * 2 + u];
        float4 w4 = w[lane * 2 + u];
        acc += h4.x * w4.x + h4.y * w4.y + h4.z * w4.z + h4.w * w4.w;
    }
#pragma unroll
    for (int u = 0; u < 2; u++) {
        float4 h4 = hb[lane * 2 + u];
        float4 w4 = w[64 + lane * 2 + u];
        acc += h4.x * w4.x + h4.y * w4.y + h4.z * w4.z + h4.w * w4.w;
    }
#pragma unroll
    for (int off = 16; off > 0; off >>= 1) acc += __shfl_xor_sync(full, acc, off);
    if (lane == 0) g_feats[bt * KK + k] = acc + b2t[k];
}

// ---------------- CRF forward + gold + final reduction ----------------
__global__ void crf_kernel(const int* __restrict__ tags, const float* __restrict__ trans,
                           float* __restrict__ out)
{
    __shared__ float res[BB];
    const int lane = threadIdx.x & 31;
    const int b = threadIdx.x >> 5;
    const unsigned full = 0xffffffffu;

    int kr = (lane < KK) ? lane : 0;
    float trow[KK];
#pragma unroll
    for (int j = 0; j < KK; j++) trow[j] = trans[kr * KK + j];

    float alpha = (lane == START_T) ? 0.0f : NEGV;

    for (int t = 0; t < TT; t++) {
        float vals[KK];
        float m = -INFINITY;
#pragma unroll
        for (int j = 0; j < KK; j++) {
            float aj = __shfl_sync(full, alpha, j);
            float v = aj + trow[j];
            vals[j] = v;
            m = fmaxf(m, v);
        }
        float s = 0.0f;
#pragma unroll
        for (int j = 0; j < KK; j++) s += expf(vals[j] - m);
        alpha = m + logf(s) + g_feats[(size_t)(b * TT + t) * KK + kr];
    }

    float v = (lane < KK) ? (alpha + trans[STOP_T * KK + lane]) : -INFINITY;
    float m = v;
#pragma unroll
    for (int off = 16; off > 0; off >>= 1) m = fmaxf(m, __shfl_xor_sync(full, m, off));
    float e = (lane < KK) ? expf(v - m) : 0.0f;
#pragma unroll
    for (int off = 16; off > 0; off >>= 1) e += __shfl_xor_sync(full, e, off);
    float fwd = m + logf(e);

    float gold = 0.0f;
    for (int t = lane; t < TT; t += 32) {
        int tg = tags[b * TT + t];
        gold += g_feats[(size_t)(b * TT + t) * KK + tg];
        int prev = (t == 0) ? START_T : tags[b * TT + t - 1];
        gold += trans[tg * KK + prev];
    }
#pragma unroll
    for (int off = 16; off > 0; off >>= 1) gold += __shfl_xor_sync(full, gold, off);

    if (lane == 0) {
        gold += trans[STOP_T * KK + tags[b * TT + TT - 1]];
        res[b] = fwd - gold;
    }
    __syncthreads();
    if (threadIdx.x == 0) {
        float s = 0.0f;
        for (int i = 0; i < BB; i++) s += res[i];
        out[0] = s / (float)BB;
    }
}

// ---------------- launch ----------------
extern "C" void kernel_launch(void* const* d_in, const int* in_sizes, int n_in,
                              void* d_out, int out_size)
{
    const int*   sentence = (const int*)d_in[0];
    const int*   chars    = (const int*)d_in[1];
    const int*   tags     = (const int*)d_in[2];
    const float* word_emb = (const float*)d_in[3];
    const float* char_emb = (const float*)d_in[4];
    const float* c_Wih_f  = (const float*)d_in[5];
    const float* c_Whh_f  = (const float*)d_in[6];
    const float* c_b_f    = (const float*)d_in[7];
    const float* c_Wih_b  = (const float*)d_in[8];
    const float* c_Whh_b  = (const float*)d_in[9];   (void)c_Whh_b;
    const float* c_b_b    = (const float*)d_in[10];
    const float* w_Wih_f  = (const float*)d_in[11];
    const float* w_Whh_f  = (const float*)d_in[12];
    const float* w_b_f    = (const float*)d_in[13];
    const float* w_Wih_b  = (const float*)d_in[14];
    const float* w_Whh_b  = (const float*)d_in[15];
    const float* w_b_b    = (const float*)d_in[16];
    const float* W2t      = (const float*)d_in[17];
    const float* b2t      = (const float*)d_in[18];
    const float* trans    = (const float*)d_in[19];
    float* out = (float*)d_out;

    float* chout; cudaGetSymbolAddress((void**)&chout, g_chout);

    // 1) char gate tables (both dirs)
    char_table_kernel<<<dim3(VCC, 2), GC>>>(char_emb, c_Wih_f, c_b_f, c_Wih_b, c_b_b);
    // 2) char BiLSTM (fwd recurrence + bwd single step), table-driven
    char_fwd_kernel<<<BT, GC>>>(chars, c_Whh_f, chout);
    // 3) build word input
    build_wx_kernel<<<(BT * INW + 255) / 256, 256>>>(sentence, word_emb);
    // 4) word input projections (both dirs in one launch)
    wproj_gemm<<<dim3(GW / 128, BT / 128, 2), 256>>>(w_Wih_f, w_b_f, w_Wih_b, w_b_b);
    // 5) barrier reset + persistent word BiLSTM
    reset_bar<<<1, 256>>>();
    word_lstm_kernel<<<NBW, 128, 48 * 1024>>>(w_Whh_f, w_Whh_b);
    // 6) feats
    feats_kernel<<<(BT * KK * 32 + 255) / 256, 256>>>(W2t, b2t);
    // 7) CRF + output
    crf_kernel<<<1, BB * 32>>>(tags, trans, out);

    (void)in_sizes; (void)n_in; (void)out_size;
}

// round 8
// speedup vs baseline: 1.8005x; 1.1977x over previous
#include <cuda_runtime.h>
#include <cuda_bf16.h>
#include <cstdint>

// ---------------- problem constants ----------------
#define BB   32
#define TT   128
#define LCC  16
#define EE   256
#define ECC  64
#define VCC  128   // char vocab
#define HCC  128   // char bilstm out (64 per dir)
#define HH   512   // word bilstm out
#define KK   12
#define START_T 10
#define STOP_T  11
#define NEGV -10000.0f

#define BT   (BB*TT)            // 4096
#define INW  (EE + HCC)         // 384
#define HW   256                // word hidden per dir
#define GW   1024               // 4*HW
#define HCD  64                 // char hidden per dir
#define GC   256                // 4*HCD
#define NBW  128                // persistent blocks (grid barrier)

// ---------------- scratch ----------------
__device__ float g_ctab_f[VCC * GC];             // per-char fwd gate table
__device__ float g_ctab_b[VCC * GC];             // per-char bwd gate table
__device__ float g_chout[(size_t)BT * HCC];
__device__ float g_wpf[(size_t)BT * GW];         // layout [t][b][n]
__device__ float g_wpb[(size_t)BT * GW];         // layout [t][b][n]
__device__ float g_h[2 * 2 * HW * BB];           // [parity][dir][j][b]
__device__ float g_wh[(size_t)2 * BT * HW];      // [dir][b*T+t][j]
__device__ float g_feats[(size_t)BT * KK];

// distributed barrier flags, padded to one 32B sector per block
__device__ unsigned g_flags[NBW * 8];

__device__ __forceinline__ float sigf(float x) { return 1.0f / (1.0f + expf(-x)); }

// ---------------- packed f32x2 helpers (sm_100+) ----------------
__device__ __forceinline__ unsigned long long fma2(unsigned long long a,
                                                   unsigned long long b,
                                                   unsigned long long c)
{
    unsigned long long d;
    asm("fma.rn.f32x2 %0, %1, %2, %3;" : "=l"(d) : "l"(a), "l"(b), "l"(c));
    return d;
}
__device__ __forceinline__ unsigned long long add2(unsigned long long a,
                                                   unsigned long long b)
{
    unsigned long long d;
    asm("add.rn.f32x2 %0, %1, %2;" : "=l"(d) : "l"(a), "l"(b));
    return d;
}
__device__ __forceinline__ unsigned long long pack2(float x, float y)
{
    unsigned long long d;
    asm("mov.b64 %0, {%1, %2};" : "=l"(d) : "f"(x), "f"(y));
    return d;
}
__device__ __forceinline__ void unpack2(unsigned long long v, float& x, float& y)
{
    asm("mov.b64 {%0, %1}, %2;" : "=f"(x), "=f"(y) : "l"(v));
}

// ---------------- char tables + barrier-flag reset (fused; launch #1) ----------------
__global__ void char_table_kernel(const float* __restrict__ char_emb,
                                  const float* __restrict__ Wih_f, const float* __restrict__ b_f,
                                  const float* __restrict__ Wih_b, const float* __restrict__ b_b)
{
    const int cid = blockIdx.x;
    const int dir = blockIdx.y;
    const int j = threadIdx.x;           // 0..255 gate index

    // fused barrier reset (block (0,0) only) — keeps replays deterministic
    if (cid == 0 && dir == 0) {
        for (int i = j; i < NBW * 8; i += GC) g_flags[i] = 0;
    }

    __shared__ float e[ECC];
    if (j < ECC) e[j] = char_emb[cid * ECC + j];
    __syncthreads();
    const float* Wih = dir ? Wih_b : Wih_f;
    const float* bias = dir ? b_b : b_f;
    const float* row = Wih + (size_t)j * ECC;
    float acc = bias[j];
#pragma unroll 8
    for (int k = 0; k < ECC; k++) acc += row[k] * e[k];
    (dir ? g_ctab_b : g_ctab_f)[cid * GC + j] = acc;
}

// ---------------- char BiLSTM (fwd recurrence + bwd single step); launch #2 ----------------
__global__ void char_fwd_kernel(const int* __restrict__ chars,
                                const float* __restrict__ Whh, float* __restrict__ chout)
{
    const int bt = blockIdx.x;
    const int j = threadIdx.x;   // 256 threads = gate index
    __shared__ __align__(16) float hs[HCD];
    __shared__ float gs[GC];
    __shared__ int cid[LCC];

    if (j < LCC) cid[j] = chars[bt * LCC + j];

    float4 w4[16];
    const float4* wr = (const float4*)(Whh + (size_t)j * HCD);
#pragma unroll
    for (int i = 0; i < 16; i++) w4[i] = wr[i];

    float c = 0.0f;
    if (j < HCD) hs[j] = 0.0f;
    __syncthreads();

    for (int t = 0; t < LCC; t++) {
        float acc = g_ctab_f[cid[t] * GC + j];
#pragma unroll
        for (int kk = 0; kk < 16; kk++) {
            float4 h4 = *(const float4*)&hs[kk << 2];
            acc += w4[kk].x * h4.x + w4[kk].y * h4.y + w4[kk].z * h4.z + w4[kk].w * h4.w;
        }
        gs[j] = acc;
        __syncthreads();
        if (j < HCD) {
            float gi = gs[j], gf = gs[HCD + j], gg = gs[2 * HCD + j], go = gs[3 * HCD + j];
            c = sigf(gf) * c + sigf(gi) * tanhf(gg);
            hs[j] = sigf(go) * tanhf(c);
        }
        __syncthreads();
    }
    if (j < HCD) {
        chout[(size_t)bt * HCC + j] = hs[j];
        // backward dir: take-last == one step on last char from zero state
        const float* row = g_ctab_b + cid[LCC - 1] * GC;
        float gi = row[j], gg = row[2 * HCD + j], go = row[3 * HCD + j];
        float cb = sigf(gi) * tanhf(gg);
        chout[(size_t)bt * HCC + HCD + j] = sigf(go) * tanhf(cb);
    }
}

// ---------------- word projection GEMM with fused input gather; launch #3 ----------------
// C[t][b][n] = concat(chout, word_emb[sentence]) @ W^T + b.
// 128x128 tile, 256 threads, 8x8 microtile, f32x2 accumulators, double-buffered smem.
#define NKT (INW / 16)   // 24 k-tiles
__global__ void __launch_bounds__(256, 2)
wproj_gemm(const float* __restrict__ Wf, const float* __restrict__ bf_,
           const float* __restrict__ Wb, const float* __restrict__ bb_,
           const int* __restrict__ sentence, const float* __restrict__ word_emb)
{
    const float* W    = blockIdx.z ? Wb : Wf;
    const float* bias = blockIdx.z ? bb_ : bf_;
    float* C          = blockIdx.z ? g_wpb : g_wpf;

    __shared__ __align__(16) float As[2][16][128];
    __shared__ __align__(16) float Bs[2][16][128];
    __shared__ int sid[128];

    const int m0 = blockIdx.y * 128;      // m = b*T + t; b fixed per block
    const int n0 = blockIdx.x * 128;
    const int bglob = blockIdx.y;
    const int tid = threadIdx.x;
    const int tx = tid & 15, ty = tid >> 4;

    if (tid < 128) sid[tid] = sentence[m0 + tid];
    __syncthreads();

    const int row0 = tid >> 2,          q0 = tid & 3;
    const int row1 = (tid + 256) >> 2,  q1 = (tid + 256) & 3;

    float4 pa0, pa1, pw0, pw1;
    // gathered A load: cols [0,128) from chout, [128,384) from word_emb[sentence]
#define WP_LDA(row, kcol)                                                        \
    (((kcol) < HCC)                                                              \
        ? *(const float4*)&g_chout[(size_t)(m0 + (row)) * HCC + (kcol)]          \
        : *(const float4*)&word_emb[(size_t)sid[row] * EE + ((kcol) - HCC)])
#define WP_LOAD(k0)                                                             \
    do {                                                                        \
        pa0 = WP_LDA(row0, (k0) + q0 * 4);                                      \
        pw0 = *(const float4*)&W[(size_t)(n0 + row0) * INW + (k0) + q0 * 4];    \
        pa1 = WP_LDA(row1, (k0) + q1 * 4);                                      \
        pw1 = *(const float4*)&W[(size_t)(n0 + row1) * INW + (k0) + q1 * 4];    \
    } while (0)
#define WP_STORE(buf)                                                           \
    do {                                                                        \
        As[buf][q0 * 4 + 0][row0] = pa0.x; As[buf][q0 * 4 + 1][row0] = pa0.y;   \
        As[buf][q0 * 4 + 2][row0] = pa0.z; As[buf][q0 * 4 + 3][row0] = pa0.w;   \
        Bs[buf][q0 * 4 + 0][row0] = pw0.x; Bs[buf][q0 * 4 + 1][row0] = pw0.y;   \
        Bs[buf][q0 * 4 + 2][row0] = pw0.z; Bs[buf][q0 * 4 + 3][row0] = pw0.w;   \
        As[buf][q1 * 4 + 0][row1] = pa1.x; As[buf][q1 * 4 + 1][row1] = pa1.y;   \
        As[buf][q1 * 4 + 2][row1] = pa1.z; As[buf][q1 * 4 + 3][row1] = pa1.w;   \
        Bs[buf][q1 * 4 + 0][row1] = pw1.x; Bs[buf][q1 * 4 + 1][row1] = pw1.y;   \
        Bs[buf][q1 * 4 + 2][row1] = pw1.z; Bs[buf][q1 * 4 + 3][row1] = pw1.w;   \
    } while (0)

    unsigned long long acc2[8][4];
#pragma unroll
    for (int i = 0; i < 8; i++)
#pragma unroll
        for (int jp = 0; jp < 4; jp++) acc2[i][jp] = 0ull;

    WP_LOAD(0);
    WP_STORE(0);
    __syncthreads();

    for (int kt = 0; kt < NKT; kt++) {
        const int cur = kt & 1;
        if (kt + 1 < NKT) WP_LOAD((kt + 1) * 16);
#pragma unroll
        for (int k = 0; k < 16; k++) {
            float4 a0 = *(const float4*)&As[cur][k][ty * 8];
            float4 a1 = *(const float4*)&As[cur][k][ty * 8 + 4];
            ulonglong2 b0 = *(const ulonglong2*)&Bs[cur][k][tx * 8];
            ulonglong2 b1 = *(const ulonglong2*)&Bs[cur][k][tx * 8 + 4];
            float aarr[8] = {a0.x, a0.y, a0.z, a0.w, a1.x, a1.y, a1.z, a1.w};
#pragma unroll
            for (int i = 0; i < 8; i++) {
                unsigned long long ad = pack2(aarr[i], aarr[i]);
                acc2[i][0] = fma2(ad, b0.x, acc2[i][0]);
                acc2[i][1] = fma2(ad, b0.y, acc2[i][1]);
                acc2[i][2] = fma2(ad, b1.x, acc2[i][2]);
                acc2[i][3] = fma2(ad, b1.y, acc2[i][3]);
            }
        }
        if (kt + 1 < NKT) {
            WP_STORE(cur ^ 1);
            __syncthreads();
        }
    }

#pragma unroll
    for (int i = 0; i < 8; i++) {
        int t = ty * 8 + i;               // local m == t (b fixed)
        size_t base = ((size_t)t * BB + bglob) * GW;
#pragma unroll
        for (int jp = 0; jp < 4; jp++) {
            int n = n0 + tx * 8 + jp * 2;
            float c0, c1;
            unpack2(acc2[i][jp], c0, c1);
            float2 v = make_float2(c0 + __ldg(&bias[n]), c1 + __ldg(&bias[n + 1]));
            *(float2*)&C[base + n] = v;
        }
    }
}

// ---------------- persistent word BiLSTM (split-K, 256 thr); launch #4 (profiled) ----------------
__global__ void word_lstm_kernel(const float* __restrict__ Whhf,
                                 const float* __restrict__ Whhb)
{
    extern __shared__ float sm[];
    float* ws = sm;                 // 4096 floats: [jh_l][k][gate(4)]
    float* hs = sm + 4096;          // 8192 floats: [k][b]; aliased as partials after use

    const int tid = threadIdx.x;          // 0..255
    const int dir = blockIdx.x >> 6;
    const int chunk = blockIdx.x & 63;
    const int jh0 = chunk * 4;
    const int b = tid & 31;
    const int half = (tid >> 5) & 1;
    const int jh_l = tid >> 6;            // 0..3
    const int jh = jh0 + jh_l;

    const float* Whh = dir ? Whhb : Whhf;
    const float* xp  = dir ? g_wpb : g_wpf;

    for (int i = tid; i < 4096; i += 256) {
        int gate = i & 3;
        int k = (i >> 2) & 255;
        int jl = i >> 10;
        ws[i] = Whh[(size_t)((gate << 8) + jh0 + jl) * HW + k];
    }
    __syncthreads();

    const ulonglong2* wv = (const ulonglong2*)ws + (jh_l << 8) + (half << 7);

    unsigned* myflag   = g_flags + blockIdx.x * 8;
    unsigned* pollflag = g_flags + (((dir << 6) + tid) * 8);   // tid<64 only

    float xi = 0.f, xf2 = 0.f, xg = 0.f, xo = 0.f;
    if (half == 0) {
        int t0 = dir ? (TT - 1) : 0;
        const float* base = xp + ((size_t)t0 * BB + b) * GW;
        xi = base[jh]; xf2 = base[HW + jh]; xg = base[2 * HW + jh]; xo = base[3 * HW + jh];
    }

    float c = 0.0f, h = 0.0f;
    for (int s = 0; s < TT; s++) {
        const int t = dir ? (TT - 1 - s) : s;
        unsigned long long acc_if = 0ull, acc_go = 0ull;
        if (s > 0) {
            const float4* hsrc = (const float4*)(g_h + (((s & 1) * 2 + dir) << 13));
            float4* hd4 = (float4*)hs;
#pragma unroll
            for (int i = tid; i < 2048; i += 256) hd4[i] = __ldcg(hsrc + i);
            __syncthreads();
            const float* hsh = hs + (half << 12);   // K-half offset
#pragma unroll 8
            for (int kl = 0; kl < 128; kl++) {
                ulonglong2 w = wv[kl];
                float hv = hsh[(kl << 5) + b];
                unsigned long long hd = pack2(hv, hv);
                acc_if = fma2(hd, w.x, acc_if);
                acc_go = fma2(hd, w.y, acc_go);
            }
            __syncthreads();   // all hs reads done before aliasing as partials
            ((ulonglong2*)hs)[tid] = make_ulonglong2(acc_if, acc_go);
            __syncthreads();
            if (half == 0) {
                ulonglong2 p = ((ulonglong2*)hs)[tid + 32];   // partner (half=1)
                acc_if = add2(acc_if, p.x);
                acc_go = add2(acc_go, p.y);
            }
        }
        if (half == 0) {
            acc_if = add2(acc_if, pack2(xi, xf2));
            acc_go = add2(acc_go, pack2(xg, xo));
            float gi, gf, gg, go;
            unpack2(acc_if, gi, gf);
            unpack2(acc_go, gg, go);
            c = sigf(gf) * c + sigf(gi) * tanhf(gg);
            h = sigf(go) * tanhf(c);
            __stcg(g_h + (((((s + 1) & 1) * 2 + dir) << 13) + (jh << 5) + b), h);
        }

        if (s + 1 < TT) {
            if (half == 0) {
                int tn = dir ? (TT - 2 - s) : (s + 1);
                const float* base = xp + ((size_t)tn * BB + b) * GW;
                xi = base[jh]; xf2 = base[HW + jh]; xg = base[2 * HW + jh]; xo = base[3 * HW + jh];
                __threadfence();   // order h store before flag store
            }
            __syncthreads();
            const unsigned want = (unsigned)(s + 1);
            if (tid == 0) {
                asm volatile("st.global.cg.u32 [%0], %1;" :: "l"(myflag), "r"(want) : "memory");
            }
            if (half == 0) g_wh[((size_t)dir * BT + b * TT + t) * HW + jh] = h;
            if (tid < 64) {   // warps 0,1: poll 64 dir-local flags, one per lane
                unsigned v;
                int sp = 0;
                for (;;) {
                    asm volatile("ld.global.cg.u32 %0, [%1];" : "=r"(v) : "l"(pollflag) : "memory");
                    if (v >= want) break;
                    if (++sp > 1024) __nanosleep(64);
                }
            }
            __syncthreads();
            __threadfence();
        } else {
            if (half == 0) g_wh[((size_t)dir * BT + b * TT + t) * HW + jh] = h;
        }
    }
}

// ---------------- feats: warp per (bt,k) dot over 512; launch #5 ----------------
__global__ void feats_kernel(const float* __restrict__ W2t, const float* __restrict__ b2t)
{
    const unsigned full = 0xffffffffu;
    int gwarp = (blockIdx.x * blockDim.x + threadIdx.x) >> 5;
    if (gwarp >= BT * KK) return;
    int lane = threadIdx.x & 31;
    int bt = gwarp / KK, k = gwarp % KK;

    const float4* hf = (const float4*)(g_wh + (size_t)bt * HW);
    const float4* hb = (const float4*)(g_wh + ((size_t)BT + bt) * HW);
    const float4* w  = (const float4*)(W2t + (size_t)k * HH);

    float acc = 0.0f;
#pragma unroll
    for (int u = 0; u < 2; u++) {
        float4 h4 = hf[lane * 2 + u];
        float4 w4 = w[lane * 2 + u];
        acc += h4.x * w4.x + h4.y * w4.y + h4.z * w4.z + h4.w * w4.w;
    }
#pragma unroll
    for (int u = 0; u < 2; u++) {
        float4 h4 = hb[lane * 2 + u];
        float4 w4 = w[64 + lane * 2 + u];
        acc += h4.x * w4.x + h4.y * w4.y + h4.z * w4.z + h4.w * w4.w;
    }
#pragma unroll
    for (int off = 16; off > 0; off >>= 1) acc += __shfl_xor_sync(full, acc, off);
    if (lane == 0) g_feats[bt * KK + k] = acc + b2t[k];
}

// ---------------- CRF forward + gold + final reduction; launch #6 ----------------
__global__ void crf_kernel(const int* __restrict__ tags, const float* __restrict__ trans,
                           float* __restrict__ out)
{
    __shared__ float res[BB];
    const int lane = threadIdx.x & 31;
    const int b = threadIdx.x >> 5;
    const unsigned full = 0xffffffffu;

    int kr = (lane < KK) ? lane : 0;
    float trow[KK];
#pragma unroll
    for (int j = 0; j < KK; j++) trow[j] = trans[kr * KK + j];

    float alpha = (lane == START_T) ? 0.0f : NEGV;

    for (int t = 0; t < TT; t++) {
        float vals[KK];
        float m = -INFINITY;
#pragma unroll
        for (int j = 0; j < KK; j++) {
            float aj = __shfl_sync(full, alpha, j);
            float v = aj + trow[j];
            vals[j] = v;
            m = fmaxf(m, v);
        }
        float s = 0.0f;
#pragma unroll
        for (int j = 0; j < KK; j++) s += expf(vals[j] - m);
        alpha = m + logf(s) + g_feats[(size_t)(b * TT + t) * KK + kr];
    }

    float v = (lane < KK) ? (alpha + trans[STOP_T * KK + lane]) : -INFINITY;
    float m = v;
#pragma unroll
    for (int off = 16; off > 0; off >>= 1) m = fmaxf(m, __shfl_xor_sync(full, m, off));
    float e = (lane < KK) ? expf(v - m) : 0.0f;
#pragma unroll
    for (int off = 16; off > 0; off >>= 1) e += __shfl_xor_sync(full, e, off);
    float fwd = m + logf(e);

    float gold = 0.0f;
    for (int t = lane; t < TT; t += 32) {
        int tg = tags[b * TT + t];
        gold += g_feats[(size_t)(b * TT + t) * KK + tg];
        int prev = (t == 0) ? START_T : tags[b * TT + t - 1];
        gold += trans[tg * KK + prev];
    }
#pragma unroll
    for (int off = 16; off > 0; off >>= 1) gold += __shfl_xor_sync(full, gold, off);

    if (lane == 0) {
        gold += trans[STOP_T * KK + tags[b * TT + TT - 1]];
        res[b] = fwd - gold;
    }
    __syncthreads();
    if (threadIdx.x == 0) {
        float s = 0.0f;
        for (int i = 0; i < BB; i++) s += res[i];
        out[0] = s / (float)BB;
    }
}

// ---------------- launch ----------------
extern "C" void kernel_launch(void* const* d_in, const int* in_sizes, int n_in,
                              void* d_out, int out_size)
{
    const int*   sentence = (const int*)d_in[0];
    const int*   chars    = (const int*)d_in[1];
    const int*   tags     = (const int*)d_in[2];
    const float* word_emb = (const float*)d_in[3];
    const float* char_emb = (const float*)d_in[4];
    const float* c_Wih_f  = (const float*)d_in[5];
    const float* c_Whh_f  = (const float*)d_in[6];
    const float* c_b_f    = (const float*)d_in[7];
    const float* c_Wih_b  = (const float*)d_in[8];
    const float* c_Whh_b  = (const float*)d_in[9];   (void)c_Whh_b;
    const float* c_b_b    = (const float*)d_in[10];
    const float* w_Wih_f  = (const float*)d_in[11];
    const float* w_Whh_f  = (const float*)d_in[12];
    const float* w_b_f    = (const float*)d_in[13];
    const float* w_Wih_b  = (const float*)d_in[14];
    const float* w_Whh_b  = (const float*)d_in[15];
    const float* w_b_b    = (const float*)d_in[16];
    const float* W2t      = (const float*)d_in[17];
    const float* b2t      = (const float*)d_in[18];
    const float* trans    = (const float*)d_in[19];
    float* out = (float*)d_out;

    float* chout; cudaGetSymbolAddress((void**)&chout, g_chout);

    // 1) char gate tables (both dirs) + fused barrier-flag reset
    char_table_kernel<<<dim3(VCC, 2), GC>>>(char_emb, c_Wih_f, c_b_f, c_Wih_b, c_b_b);
    // 2) char BiLSTM (fwd recurrence + bwd single step), table-driven
    char_fwd_kernel<<<BT, GC>>>(chars, c_Whh_f, chout);
    // 3) word input projections with fused gather (both dirs)
    wproj_gemm<<<dim3(GW / 128, BT / 128, 2), 256>>>(w_Wih_f, w_b_f, w_Wih_b, w_b_b,
                                                     sentence, word_emb);
    // 4) persistent word BiLSTM (4th launch -> gets profiled)
    word_lstm_kernel<<<NBW, 256, 48 * 1024>>>(w_Whh_f, w_Whh_b);
    // 5) feats
    feats_kernel<<<(BT * KK * 32 + 255) / 256, 256>>>(W2t, b2t);
    // 6) CRF + output
    crf_kernel<<<1, BB * 32>>>(tags, trans, out);

    (void)in_sizes; (void)n_in; (void)out_size;
}